// round 8
// baseline (speedup 1.0000x reference)
#include <cuda_runtime.h>
#include <cuda_fp16.h>

#define NB 8
#define NN 1024
#define NF 128
#define NH 8

// -------- scratch (device globals; allocation is forbidden) --------
__device__ __half    g_Q[NB*NN*NF];      // [b*N+q][128], pre-scaled by log2e/4
__device__ __half    g_K[NB*NN*NF];      // [b*N+q][128]
__device__ __half    g_V[NB*NN*NF];      // [b][t16=q/16][o(128)][qi(16)]  (16-key tiled)
__device__ unsigned  g_mask[NB*NN*32];   // [b*N+q][word]; bit j of word w = A[..][w*32+j]>0

#define QSCALE 0.3606737602222409f   // log2(e)/4
#define ONES2  0x3C003C00u           // half2(1,1)

// attn smem layout (bytes)
#define SM_WOS   0        // Wos[128][136] half   = 34816
#define SM_XS    34816    // Xs[32][136]  half    = 8704
#define SM_MASK  43520    // smask[32][33] u32    = 4224
#define SM_BS    47744    // bs[128] float        = 512
#define SM_KS    48256    // Ks[2][32][136] half  = 17408  (8704/buf)
#define SM_VS    65664    // Vs[2][128][40] half  = 20480  (10240/buf)
#define SM_TOT   86144

// -------- helpers --------
static __device__ __forceinline__ float rcpf(float x){ float r; asm("rcp.approx.ftz.f32 %0,%1;":"=f"(r):"f"(x)); return r; }
static __device__ __forceinline__ unsigned h2(float a,float b){
    __half2 h = __floats2half2_rn(a,b); return *reinterpret_cast<unsigned*>(&h); }
static __device__ __forceinline__ unsigned hex2(unsigned x){
    unsigned r; asm("ex2.approx.f16x2 %0,%1;":"=r"(r):"r"(x)); return r; }
// expand low 2 bits -> per-half 0xFFFF masks
static __device__ __forceinline__ unsigned mpat(unsigned bits){
    unsigned t = (bits & 3u) * 0x4080u;
    unsigned r; asm("prmt.b32 %0,%1,%2,%3;":"=r"(r):"r"(t),"r"(0u),"r"(0x9988u));
    return r;
}
static __device__ __forceinline__ void mma16816(float c[4], const unsigned a[4], unsigned b0, unsigned b1){
    asm volatile("mma.sync.aligned.m16n8k16.row.col.f32.f16.f16.f32 "
                 "{%0,%1,%2,%3},{%4,%5,%6,%7},{%8,%9},{%0,%1,%2,%3};"
                 : "+f"(c[0]),"+f"(c[1]),"+f"(c[2]),"+f"(c[3])
                 : "r"(a[0]),"r"(a[1]),"r"(a[2]),"r"(a[3]),"r"(b0),"r"(b1));
}
static __device__ __forceinline__ void ldm4(unsigned r[4], unsigned addr){
    asm volatile("ldmatrix.sync.aligned.m8n8.x4.shared.b16 {%0,%1,%2,%3}, [%4];"
        : "=r"(r[0]),"=r"(r[1]),"=r"(r[2]),"=r"(r[3]) : "r"(addr));
}
static __device__ __forceinline__ void cpa16(unsigned dst, const void* src){
    asm volatile("cp.async.cg.shared.global [%0], [%1], 16;" :: "r"(dst), "l"(src) : "memory");
}

// ============ kernel 1: fused mask compaction + Q/K/V projections ============
__global__ __launch_bounds__(512) void pre_kernel(const float* __restrict__ X,
        const float* __restrict__ A,
        const float* __restrict__ Wq, const float* __restrict__ bq,
        const float* __restrict__ Wk, const float* __restrict__ bk,
        const float* __restrict__ Wv, const float* __restrict__ bv){
    int bid = blockIdx.x;
    int tid = threadIdx.x;
    int w = tid >> 5, lane = tid & 31;

    if (bid >= 192){
        int row = (bid - 192) * 16 + w;               // 0..8191 (b*N+q)
        const float* a = A + (size_t)row * NN;
        unsigned myw = 0;
        #pragma unroll
        for (int j = 0; j < 32; ++j){
            unsigned m = __ballot_sync(0xffffffffu, a[j*32 + lane] > 0.0f);
            if (lane == j) myw = m;
        }
        g_mask[(size_t)row * 32 + lane] = myw;
        return;
    }

    extern __shared__ char smem[];
    __half (*Xs)[136] = (__half(*)[136])smem;
    __half (*Ws)[136] = (__half(*)[136])(smem + 34816);
    float*  bs        = (float*)(smem + 69632);

    int mode = bid >> 6;        // 0=Q 1=K 2=V
    int tile = bid & 63;
    const float* Wp = (mode == 0) ? Wq : (mode == 1) ? Wk : Wv;
    const float* bp = (mode == 0) ? bq : (mode == 1) ? bk : bv;
    int row0 = tile * 128;

    for (int i = tid; i < 4096; i += 512){
        int r = i >> 5, c4 = (i & 31) * 4;
        float4 v = *(const float4*)&X[(size_t)(row0 + r)*NF + c4];
        uint2 u; u.x = h2(v.x, v.y); u.y = h2(v.z, v.w);
        *(uint2*)&Xs[r][c4] = u;
        float4 ww = *(const float4*)&Wp[(size_t)r*NF + c4];
        uint2 uw; uw.x = h2(ww.x, ww.y); uw.y = h2(ww.z, ww.w);
        *(uint2*)&Ws[r][c4] = uw;
    }
    if (tid < 128) bs[tid] = bp[tid];
    __syncthreads();

    int qr = lane >> 2, lc = lane & 3, ms = lc * 2;
    int rg = w >> 1, ch = w & 1;

    const unsigned* Ab = (mode == 2) ? (const unsigned*)Ws : (const unsigned*)Xs;
    const unsigned* Bb = (mode == 2) ? (const unsigned*)Xs : (const unsigned*)Ws;

    unsigned a[8][4];
    {
        const unsigned* p = Ab + (16*rg + qr)*68 + lc;
        #pragma unroll
        for (int kt = 0; kt < 8; ++kt){
            a[kt][0] = p[kt*8];
            a[kt][1] = p[kt*8 + 8*68];
            a[kt][2] = p[kt*8 + 4];
            a[kt][3] = p[kt*8 + 8*68 + 4];
        }
    }

    float c[8][4];
    #pragma unroll
    for (int j = 0; j < 8; ++j){ c[j][0]=0.f; c[j][1]=0.f; c[j][2]=0.f; c[j][3]=0.f; }
    #pragma unroll
    for (int j = 0; j < 8; ++j){
        const unsigned* bpq = Bb + (64*ch + 8*j + qr)*68 + lc;
        #pragma unroll
        for (int kt = 0; kt < 8; ++kt)
            mma16816(c[j], a[kt], bpq[kt*8], bpq[kt*8 + 4]);
    }

    int b = row0 >> 10, q0 = row0 & (NN - 1);
    #pragma unroll
    for (int j = 0; j < 8; ++j){
        if (mode == 2){
            int o0 = 16*rg + qr, o1 = o0 + 8;
            int qg = q0 + 64*ch + 8*j + ms;        // global q within batch
            int t16 = qg >> 4, qi = qg & 15;
            float b0 = bs[o0], b1 = bs[o1];
            __half* base = g_V + ((size_t)(b*64 + t16) * 128) * 16;
            *(unsigned*)&base[o0*16 + qi] = h2(c[j][0]+b0, c[j][1]+b0);
            *(unsigned*)&base[o1*16 + qi] = h2(c[j][2]+b1, c[j][3]+b1);
        } else {
            int col = 64*ch + 8*j + ms;
            float b0 = bs[col], b1 = bs[col + 1];
            int r = row0 + 16*rg + qr;
            if (mode == 0){
                *(unsigned*)&g_Q[(size_t)r*NF + col]     = h2((c[j][0]+b0)*QSCALE, (c[j][1]+b1)*QSCALE);
                *(unsigned*)&g_Q[(size_t)(r+8)*NF + col] = h2((c[j][2]+b0)*QSCALE, (c[j][3]+b1)*QSCALE);
            } else {
                *(unsigned*)&g_K[(size_t)r*NF + col]     = h2(c[j][0]+b0, c[j][1]+b1);
                *(unsigned*)&g_K[(size_t)(r+8)*NF + col] = h2(c[j][2]+b0, c[j][3]+b1);
            }
        }
    }
}

// ============ kernel 2: masked flash attention + fused output projection ============
// grid 256 (b, q0-tile of 32), 256 threads: warp = head, 32 query rows
// 2 blocks co-resident per SM -> independent barrier groups
__global__ __launch_bounds__(256) void attn_kernel(const float* __restrict__ Wo,
        const float* __restrict__ bo, float* __restrict__ out){
    extern __shared__ char smem[];
    __half   (*Wos)[136]  = (__half(*)[136])(smem + SM_WOS);
    __half   (*Xs)[136]   = (__half(*)[136])(smem + SM_XS);
    unsigned (*smask)[33] = (unsigned(*)[33])(smem + SM_MASK);
    float*    bs          = (float*)(smem + SM_BS);
    const unsigned smem_u = (unsigned)__cvta_generic_to_shared(smem);

    int tid = threadIdx.x;
    int b  = blockIdx.x >> 5;
    int q0 = (blockIdx.x & 31) * 32;
    int wid = tid >> 5, lane = tid & 31;
    int h = wid;                                   // warp = head

    // stage Wo (fp32->fp16), bias, mask
    for (int i = tid; i < 4096; i += 256){
        int r = i >> 5, c4 = (i & 31) * 4;
        float4 v = *(const float4*)&Wo[(size_t)r*NF + c4];
        uint2 u; u.x = h2(v.x, v.y); u.y = h2(v.z, v.w);
        *(uint2*)&Wos[r][c4] = u;
    }
    if (tid < 128) bs[tid] = bo[tid];
    for (int i = tid; i < 1024; i += 256){
        int r = i >> 5, ww = i & 31;
        smask[r][ww] = g_mask[(size_t)((b<<10) + q0 + r)*32 + ww];
    }

    int qr = lane >> 2;
    int lc = lane & 3;
    int ms = lc * 2;

    unsigned a[2][4];
    #pragma unroll
    for (int f=0; f<2; ++f){
        const __half* Qp = g_Q + (((size_t)((b<<10) + q0 + f*16 + qr)) << 7) + h*16;
        a[f][0] = *(const unsigned*)(Qp + ms);
        a[f][2] = *(const unsigned*)(Qp + ms + 8);
        const __half* Qp8 = Qp + (8 << 7);
        a[f][1] = *(const unsigned*)(Qp8 + ms);
        a[f][3] = *(const unsigned*)(Qp8 + ms + 8);
    }

    float o[2][2][4];
    float lsum[2][4];
    #pragma unroll
    for (int f=0;f<2;++f){
        #pragma unroll
        for (int j=0;j<4;++j) lsum[f][j]=0.f;
        #pragma unroll
        for (int t=0;t<2;++t){ o[f][t][0]=0.f;o[f][t][1]=0.f;o[f][t][2]=0.f;o[f][t][3]=0.f; }
    }

    // per-thread staging descriptors (256 threads, 2 passes each for K and V)
    const int krow = tid >> 3, kch = tid & 7;        // K: 32 rows x (8 chunks x2)
    const int vo = tid >> 1, vc = tid & 1;           // V: 128 rows x (2 chunks x2)
    const unsigned kdst = smem_u + SM_KS + (krow*136 + kch*8)*2;
    const unsigned vdst = smem_u + SM_VS + (vo*40)*2;
    const __half* ksrc0 = g_K + ((size_t)(b<<10) + krow)*NF + kch*8;
    const __half* vsrc0 = g_V + ((size_t)(b*64)*128 + vo)*16 + vc*8;

    #define STAGE(it, buf) do { \
        const __half* ks = ksrc0 + (size_t)(it)*32*NF; \
        cpa16(kdst + (buf)*8704,        ks); \
        cpa16(kdst + (buf)*8704 + 128,  ks + 64); \
        const __half* vs = vsrc0 + (size_t)(it)*2*2048; \
        cpa16(vdst + (buf)*10240 + vc*16,        vs); \
        cpa16(vdst + (buf)*10240 + (vc+2)*16,    vs + 2048); \
        asm volatile("cp.async.commit_group;" ::: "memory"); \
    } while(0)

    STAGE(0, 0);
    STAGE(1, 1);

    // per-thread ldmatrix address offsets (within a buffer)
    const unsigned kfrag = smem_u + SM_KS +
        ((((lane>>4)&1)*8 + (lane&7))*136 + h*16 + ((lane>>3)&1)*8)*2;
    const unsigned vfrag = smem_u + SM_VS +
        ((h*16 + ((lane>>4)&1)*8 + (lane&7))*40 + ((lane>>3)&1)*8)*2;

    for (int it = 0; it < 32; ++it){
        int buf = it & 1;
        if (it < 31) asm volatile("cp.async.wait_group 1;" ::: "memory");
        else         asm volatile("cp.async.wait_group 0;" ::: "memory");
        __syncthreads();

        #pragma unroll
        for (int sub = 0; sub < 2; ++sub){
            unsigned kb[4], vb[4];
            ldm4(kb, kfrag + buf*8704 + sub*16*136*2);
            ldm4(vb, vfrag + buf*10240 + sub*32);
            int sbms = (sub << 4) + ms;
            #pragma unroll
            for (int f=0; f<2; ++f){
                float c0[4] = {0.f,0.f,0.f,0.f};
                float c1[4] = {0.f,0.f,0.f,0.f};
                mma16816(c0, a[f], kb[0], kb[1]);
                mma16816(c1, a[f], kb[2], kb[3]);
                unsigned mlo = smask[f*16 + qr][it]     >> sbms;
                unsigned mhi = smask[f*16 + 8 + qr][it] >> sbms;
                unsigned ap[4];
                ap[0] = hex2(h2(c0[0], c0[1])) & mpat(mlo);
                ap[1] = hex2(h2(c0[2], c0[3])) & mpat(mhi);
                ap[2] = hex2(h2(c1[0], c1[1])) & mpat(mlo >> 8);
                ap[3] = hex2(h2(c1[2], c1[3])) & mpat(mhi >> 8);
                mma16816(o[f][0], ap, vb[0], vb[1]);
                mma16816(o[f][1], ap, vb[2], vb[3]);
                mma16816(lsum[f], ap, ONES2, ONES2);
            }
        }
        __syncthreads();
        if (it + 2 <= 31) STAGE(it + 2, buf);
    }

    // normalize and stage attn output tile (fp16) to smem
    #pragma unroll
    for (int f=0; f<2; ++f){
        float inv0 = rcpf(lsum[f][0]);
        float inv1 = rcpf(lsum[f][2]);
        #pragma unroll
        for (int t=0; t<2; ++t){
            *(unsigned*)&Xs[f*16 + qr][h*16 + t*8 + ms]     = h2(o[f][t][0]*inv0, o[f][t][1]*inv0);
            *(unsigned*)&Xs[f*16 + 8 + qr][h*16 + t*8 + ms] = h2(o[f][t][2]*inv1, o[f][t][3]*inv1);
        }
    }
    __syncthreads();

    // ---- fused output projection: out(32x128) = Xs @ Wos^T + bo ----
    int rg = wid >> 2, cq = wid & 3;   // 2 row groups x 4 col quarters
    unsigned a2[8][4];
    {
        const unsigned* p = (const unsigned*)Xs + (16*rg + qr)*68 + lc;
        #pragma unroll
        for (int kt = 0; kt < 8; ++kt){
            a2[kt][0] = p[kt*8];
            a2[kt][1] = p[kt*8 + 8*68];
            a2[kt][2] = p[kt*8 + 4];
            a2[kt][3] = p[kt*8 + 8*68 + 4];
        }
    }
    #pragma unroll
    for (int j = 0; j < 4; ++j){
        float c[4] = {0.f,0.f,0.f,0.f};
        const unsigned* bp = (const unsigned*)Wos + (32*cq + 8*j + qr)*68 + lc;
        #pragma unroll
        for (int kt = 0; kt < 8; ++kt)
            mma16816(c, a2[kt], bp[kt*8], bp[kt*8 + 4]);
        int col = 32*cq + 8*j + ms;
        float b0 = bs[col], b1 = bs[col + 1];
        int r = (b<<10) + q0 + 16*rg + qr;
        *(float2*)&out[(size_t)r*NF + col]     = make_float2(c[0]+b0, c[1]+b1);
        *(float2*)&out[(size_t)(r+8)*NF + col] = make_float2(c[2]+b0, c[3]+b1);
    }
}

// -------- launcher --------
extern "C" void kernel_launch(void* const* d_in, const int* in_sizes, int n_in,
                              void* d_out, int out_size){
    const float* X  = (const float*)d_in[0];
    const float* A  = (const float*)d_in[1];
    const float* Wq = (const float*)d_in[2];
    const float* bq = (const float*)d_in[3];
    const float* Wk = (const float*)d_in[4];
    const float* bk = (const float*)d_in[5];
    const float* Wv = (const float*)d_in[6];
    const float* bv = (const float*)d_in[7];
    const float* Wo = (const float*)d_in[8];
    const float* bo = (const float*)d_in[9];
    float* out = (float*)d_out;

    const int SMEM1 = 70144;
    cudaFuncSetAttribute(pre_kernel,  cudaFuncAttributeMaxDynamicSharedMemorySize, SMEM1);
    cudaFuncSetAttribute(attn_kernel, cudaFuncAttributeMaxDynamicSharedMemorySize, SM_TOT);

    pre_kernel<<<704, 512, SMEM1>>>(X, A, Wq, bq, Wk, bk, Wv, bv);
    attn_kernel<<<256, 256, SM_TOT>>>(Wo, bo, out);
}

// round 9
// speedup vs baseline: 1.1352x; 1.1352x over previous
#include <cuda_runtime.h>
#include <cuda_fp16.h>

#define NB 8
#define NN 1024
#define NF 128
#define NH 8

// -------- scratch (device globals; allocation is forbidden) --------
__device__ __half    g_Q[NB*NN*NF];      // [b*N+q][128], pre-scaled by log2e/4
__device__ __half    g_K[NB*NN*NF];      // [b*N+q][128]
__device__ __half    g_V[NB*NN*NF];      // [b][t16=q/16][o(128)][qi(16)]  (16-key tiled)
__device__ unsigned  g_mask[NB*NN*32];   // [b*N+q][word]; bit j of word w = A[..][w*32+j]>0

#define QSCALE 0.3606737602222409f   // log2(e)/4
#define ONES2  0x3C003C00u           // half2(1,1)

// attn smem layout (bytes) — triple-buffered K/V
#define SM_WOS   0        // Wos[128][136] half   = 34816
#define SM_XS    34816    // Xs[64][136]  half    = 17408
#define SM_MASK  52224    // smask[64][33] u32    = 8448
#define SM_BS    60672    // bs[128] float        = 512
#define SM_KS    61184    // Ks[3][32][136] half  = 26112  (8704/buf)
#define SM_VS    87296    // Vs[3][128][40] half  = 30720  (10240/buf)
#define SM_TOT   118016

// -------- helpers --------
static __device__ __forceinline__ float rcpf(float x){ float r; asm("rcp.approx.ftz.f32 %0,%1;":"=f"(r):"f"(x)); return r; }
static __device__ __forceinline__ unsigned h2(float a,float b){
    __half2 h = __floats2half2_rn(a,b); return *reinterpret_cast<unsigned*>(&h); }
static __device__ __forceinline__ unsigned hex2(unsigned x){
    unsigned r; asm("ex2.approx.f16x2 %0,%1;":"=r"(r):"r"(x)); return r; }
// expand low 2 bits -> per-half 0xFFFF masks
static __device__ __forceinline__ unsigned mpat(unsigned bits){
    unsigned t = (bits & 3u) * 0x4080u;
    unsigned r; asm("prmt.b32 %0,%1,%2,%3;":"=r"(r):"r"(t),"r"(0u),"r"(0x9988u));
    return r;
}
static __device__ __forceinline__ void mma16816(float c[4], const unsigned a[4], unsigned b0, unsigned b1){
    asm volatile("mma.sync.aligned.m16n8k16.row.col.f32.f16.f16.f32 "
                 "{%0,%1,%2,%3},{%4,%5,%6,%7},{%8,%9},{%0,%1,%2,%3};"
                 : "+f"(c[0]),"+f"(c[1]),"+f"(c[2]),"+f"(c[3])
                 : "r"(a[0]),"r"(a[1]),"r"(a[2]),"r"(a[3]),"r"(b0),"r"(b1));
}
static __device__ __forceinline__ void ldm4(unsigned r[4], unsigned addr){
    asm volatile("ldmatrix.sync.aligned.m8n8.x4.shared.b16 {%0,%1,%2,%3}, [%4];"
        : "=r"(r[0]),"=r"(r[1]),"=r"(r[2]),"=r"(r[3]) : "r"(addr));
}
static __device__ __forceinline__ void cpa16(unsigned dst, const void* src){
    asm volatile("cp.async.cg.shared.global [%0], [%1], 16;" :: "r"(dst), "l"(src) : "memory");
}

// ============ kernel 1: fused mask compaction + Q/K/V projections ============
__global__ __launch_bounds__(512) void pre_kernel(const float* __restrict__ X,
        const float* __restrict__ A,
        const float* __restrict__ Wq, const float* __restrict__ bq,
        const float* __restrict__ Wk, const float* __restrict__ bk,
        const float* __restrict__ Wv, const float* __restrict__ bv){
    int bid = blockIdx.x;
    int tid = threadIdx.x;
    int w = tid >> 5, lane = tid & 31;

    if (bid >= 192){
        int row = (bid - 192) * 16 + w;               // 0..8191 (b*N+q)
        const float* a = A + (size_t)row * NN;
        unsigned myw = 0;
        #pragma unroll
        for (int j = 0; j < 32; ++j){
            unsigned m = __ballot_sync(0xffffffffu, a[j*32 + lane] > 0.0f);
            if (lane == j) myw = m;
        }
        g_mask[(size_t)row * 32 + lane] = myw;
        return;
    }

    extern __shared__ char smem[];
    __half (*Xs)[136] = (__half(*)[136])smem;
    __half (*Ws)[136] = (__half(*)[136])(smem + 34816);
    float*  bs        = (float*)(smem + 69632);

    int mode = bid >> 6;        // 0=Q 1=K 2=V
    int tile = bid & 63;
    const float* Wp = (mode == 0) ? Wq : (mode == 1) ? Wk : Wv;
    const float* bp = (mode == 0) ? bq : (mode == 1) ? bk : bv;
    int row0 = tile * 128;

    for (int i = tid; i < 4096; i += 512){
        int r = i >> 5, c4 = (i & 31) * 4;
        float4 v = *(const float4*)&X[(size_t)(row0 + r)*NF + c4];
        uint2 u; u.x = h2(v.x, v.y); u.y = h2(v.z, v.w);
        *(uint2*)&Xs[r][c4] = u;
        float4 ww = *(const float4*)&Wp[(size_t)r*NF + c4];
        uint2 uw; uw.x = h2(ww.x, ww.y); uw.y = h2(ww.z, ww.w);
        *(uint2*)&Ws[r][c4] = uw;
    }
    if (tid < 128) bs[tid] = bp[tid];
    __syncthreads();

    int qr = lane >> 2, lc = lane & 3, ms = lc * 2;
    int rg = w >> 1, ch = w & 1;

    const unsigned* Ab = (mode == 2) ? (const unsigned*)Ws : (const unsigned*)Xs;
    const unsigned* Bb = (mode == 2) ? (const unsigned*)Xs : (const unsigned*)Ws;

    unsigned a[8][4];
    {
        const unsigned* p = Ab + (16*rg + qr)*68 + lc;
        #pragma unroll
        for (int kt = 0; kt < 8; ++kt){
            a[kt][0] = p[kt*8];
            a[kt][1] = p[kt*8 + 8*68];
            a[kt][2] = p[kt*8 + 4];
            a[kt][3] = p[kt*8 + 8*68 + 4];
        }
    }

    float c[8][4];
    #pragma unroll
    for (int j = 0; j < 8; ++j){ c[j][0]=0.f; c[j][1]=0.f; c[j][2]=0.f; c[j][3]=0.f; }
    #pragma unroll
    for (int j = 0; j < 8; ++j){
        const unsigned* bpq = Bb + (64*ch + 8*j + qr)*68 + lc;
        #pragma unroll
        for (int kt = 0; kt < 8; ++kt)
            mma16816(c[j], a[kt], bpq[kt*8], bpq[kt*8 + 4]);
    }

    int b = row0 >> 10, q0 = row0 & (NN - 1);
    #pragma unroll
    for (int j = 0; j < 8; ++j){
        if (mode == 2){
            int o0 = 16*rg + qr, o1 = o0 + 8;
            int qg = q0 + 64*ch + 8*j + ms;        // global q within batch
            int t16 = qg >> 4, qi = qg & 15;
            float b0 = bs[o0], b1 = bs[o1];
            __half* base = g_V + ((size_t)(b*64 + t16) * 128) * 16;
            *(unsigned*)&base[o0*16 + qi] = h2(c[j][0]+b0, c[j][1]+b0);
            *(unsigned*)&base[o1*16 + qi] = h2(c[j][2]+b1, c[j][3]+b1);
        } else {
            int col = 64*ch + 8*j + ms;
            float b0 = bs[col], b1 = bs[col + 1];
            int r = row0 + 16*rg + qr;
            if (mode == 0){
                *(unsigned*)&g_Q[(size_t)r*NF + col]     = h2((c[j][0]+b0)*QSCALE, (c[j][1]+b1)*QSCALE);
                *(unsigned*)&g_Q[(size_t)(r+8)*NF + col] = h2((c[j][2]+b0)*QSCALE, (c[j][3]+b1)*QSCALE);
            } else {
                *(unsigned*)&g_K[(size_t)r*NF + col]     = h2(c[j][0]+b0, c[j][1]+b1);
                *(unsigned*)&g_K[(size_t)(r+8)*NF + col] = h2(c[j][2]+b0, c[j][3]+b1);
            }
        }
    }
}

// ============ kernel 2: masked flash attention + fused output projection ============
// grid 128 (b, q0-tile of 64), 512 threads: warp = (half, head)
// K/V triple-buffered via cp.async, ONE barrier per iteration, LDSM hoisted
__global__ __launch_bounds__(512) void attn_kernel(const float* __restrict__ Wo,
        const float* __restrict__ bo, float* __restrict__ out){
    extern __shared__ char smem[];
    __half   (*Wos)[136]  = (__half(*)[136])(smem + SM_WOS);
    __half   (*Xs)[136]   = (__half(*)[136])(smem + SM_XS);
    unsigned (*smask)[33] = (unsigned(*)[33])(smem + SM_MASK);
    float*    bs          = (float*)(smem + SM_BS);
    const unsigned smem_u = (unsigned)__cvta_generic_to_shared(smem);

    int tid = threadIdx.x;
    int b  = blockIdx.x >> 4;
    int q0 = (blockIdx.x & 15) * 64;
    int wid = tid >> 5, lane = tid & 31;
    int h = wid & 7, half = wid >> 3;

    // stage Wo (fp32->fp16), bias, mask
    for (int i = tid; i < 4096; i += 512){
        int r = i >> 5, c4 = (i & 31) * 4;
        float4 v = *(const float4*)&Wo[(size_t)r*NF + c4];
        uint2 u; u.x = h2(v.x, v.y); u.y = h2(v.z, v.w);
        *(uint2*)&Wos[r][c4] = u;
    }
    if (tid < 128) bs[tid] = bo[tid];
    for (int i = tid; i < 2048; i += 512){
        int r = i >> 5, ww = i & 31;
        smask[r][ww] = g_mask[(size_t)((b<<10) + q0 + r)*32 + ww];
    }

    int qr = lane >> 2;
    int lc = lane & 3;
    int ms = lc * 2;
    int rbase = 32*half;

    unsigned a[2][4];
    #pragma unroll
    for (int f=0; f<2; ++f){
        const __half* Qp = g_Q + (((size_t)((b<<10) + q0 + rbase + f*16 + qr)) << 7) + h*16;
        a[f][0] = *(const unsigned*)(Qp + ms);
        a[f][2] = *(const unsigned*)(Qp + ms + 8);
        const __half* Qp8 = Qp + (8 << 7);
        a[f][1] = *(const unsigned*)(Qp8 + ms);
        a[f][3] = *(const unsigned*)(Qp8 + ms + 8);
    }

    float o[2][2][4];
    float lsum[2][4];
    #pragma unroll
    for (int f=0;f<2;++f){
        #pragma unroll
        for (int j=0;j<4;++j) lsum[f][j]=0.f;
        #pragma unroll
        for (int t=0;t<2;++t){ o[f][t][0]=0.f;o[f][t][1]=0.f;o[f][t][2]=0.f;o[f][t][3]=0.f; }
    }

    // per-thread staging descriptors (512 threads: 1 cp.async for K, 1 for V per tile)
    const int krow = tid >> 4, kch = tid & 15;               // K: 32 rows x 16 chunks
    const int vo = tid >> 2, vc = tid & 3;                   // V: 128 rows x 4 chunks
    const unsigned kdst = smem_u + SM_KS + (krow*136 + kch*8)*2;
    const unsigned vdst = smem_u + SM_VS + (vo*40 + vc*8)*2;
    const __half* ksrc0 = g_K + ((size_t)(b<<10) + krow)*NF + kch*8;
    const __half* vsrc0 = g_V + ((size_t)(b*64 + (vc>>1))*128 + vo)*16 + (vc&1)*8;

    #define STAGE(it, buf) do { \
        cpa16(kdst + (buf)*8704,  ksrc0 + (size_t)(it)*32*NF); \
        cpa16(vdst + (buf)*10240, vsrc0 + (size_t)(it)*2*2048); \
        asm volatile("cp.async.commit_group;" ::: "memory"); \
    } while(0)

    STAGE(0, 0);
    STAGE(1, 1);

    // per-thread ldmatrix address offsets (within a buffer)
    const unsigned kfrag = smem_u + SM_KS +
        ((((lane>>4)&1)*8 + (lane&7))*136 + h*16 + ((lane>>3)&1)*8)*2;
    const unsigned vfrag = smem_u + SM_VS +
        ((h*16 + ((lane>>4)&1)*8 + (lane&7))*40 + ((lane>>3)&1)*8)*2;

    int buf = 0;
    for (int it = 0; it < 32; ++it){
        if (it < 31) asm volatile("cp.async.wait_group 1;" ::: "memory");
        else         asm volatile("cp.async.wait_group 0;" ::: "memory");
        __syncthreads();

        // stage it+2 into buffer (it+2)%3 = buffer read at it-1 (safe: all warps
        // passed sync(it), so compute(it-1) is complete block-wide)
        if (it + 2 <= 31){
            int nbuf = buf + 2; if (nbuf >= 3) nbuf -= 3;
            STAGE(it + 2, nbuf);
        }

        // hoisted fragment loads: both key-subtiles of K and V back-to-back
        unsigned kb[2][4], vb[2][4];
        ldm4(kb[0], kfrag + buf*8704);
        ldm4(kb[1], kfrag + buf*8704 + 16*136*2);
        ldm4(vb[0], vfrag + buf*10240);
        ldm4(vb[1], vfrag + buf*10240 + 32);

        #pragma unroll
        for (int sub = 0; sub < 2; ++sub){
            int sbms = (sub << 4) + ms;
            #pragma unroll
            for (int f=0; f<2; ++f){
                float c0[4] = {0.f,0.f,0.f,0.f};
                float c1[4] = {0.f,0.f,0.f,0.f};
                mma16816(c0, a[f], kb[sub][0], kb[sub][1]);
                mma16816(c1, a[f], kb[sub][2], kb[sub][3]);
                unsigned mlo = smask[rbase + f*16 + qr][it]     >> sbms;
                unsigned mhi = smask[rbase + f*16 + 8 + qr][it] >> sbms;
                unsigned ap[4];
                ap[0] = hex2(h2(c0[0], c0[1])) & mpat(mlo);
                ap[1] = hex2(h2(c0[2], c0[3])) & mpat(mhi);
                ap[2] = hex2(h2(c1[0], c1[1])) & mpat(mlo >> 8);
                ap[3] = hex2(h2(c1[2], c1[3])) & mpat(mhi >> 8);
                mma16816(o[f][0], ap, vb[sub][0], vb[sub][1]);
                mma16816(o[f][1], ap, vb[sub][2], vb[sub][3]);
                mma16816(lsum[f], ap, ONES2, ONES2);
            }
        }
        ++buf; if (buf >= 3) buf = 0;
    }

    // normalize and stage attn output tile (fp16) to smem
    #pragma unroll
    for (int f=0; f<2; ++f){
        float inv0 = rcpf(lsum[f][0]);
        float inv1 = rcpf(lsum[f][2]);
        #pragma unroll
        for (int t=0; t<2; ++t){
            *(unsigned*)&Xs[rbase + f*16 + qr][h*16 + t*8 + ms]     = h2(o[f][t][0]*inv0, o[f][t][1]*inv0);
            *(unsigned*)&Xs[rbase + f*16 + 8 + qr][h*16 + t*8 + ms] = h2(o[f][t][2]*inv1, o[f][t][3]*inv1);
        }
    }
    __syncthreads();

    // ---- fused output projection: out(64x128) = Xs @ Wos^T + bo ----
    int rg = wid >> 2, cq = wid & 3;
    unsigned a2[8][4];
    {
        const unsigned* p = (const unsigned*)Xs + (16*rg + qr)*68 + lc;
        #pragma unroll
        for (int kt = 0; kt < 8; ++kt){
            a2[kt][0] = p[kt*8];
            a2[kt][1] = p[kt*8 + 8*68];
            a2[kt][2] = p[kt*8 + 4];
            a2[kt][3] = p[kt*8 + 8*68 + 4];
        }
    }
    #pragma unroll
    for (int j = 0; j < 4; ++j){
        float c[4] = {0.f,0.f,0.f,0.f};
        const unsigned* bp = (const unsigned*)Wos + (32*cq + 8*j + qr)*68 + lc;
        #pragma unroll
        for (int kt = 0; kt < 8; ++kt)
            mma16816(c, a2[kt], bp[kt*8], bp[kt*8 + 4]);
        int col = 32*cq + 8*j + ms;
        float b0 = bs[col], b1 = bs[col + 1];
        int r = (b<<10) + q0 + 16*rg + qr;
        *(float2*)&out[(size_t)r*NF + col]     = make_float2(c[0]+b0, c[1]+b1);
        *(float2*)&out[(size_t)(r+8)*NF + col] = make_float2(c[2]+b0, c[3]+b1);
    }
}

// -------- launcher --------
extern "C" void kernel_launch(void* const* d_in, const int* in_sizes, int n_in,
                              void* d_out, int out_size){
    const float* X  = (const float*)d_in[0];
    const float* A  = (const float*)d_in[1];
    const float* Wq = (const float*)d_in[2];
    const float* bq = (const float*)d_in[3];
    const float* Wk = (const float*)d_in[4];
    const float* bk = (const float*)d_in[5];
    const float* Wv = (const float*)d_in[6];
    const float* bv = (const float*)d_in[7];
    const float* Wo = (const float*)d_in[8];
    const float* bo = (const float*)d_in[9];
    float* out = (float*)d_out;

    const int SMEM1 = 70144;
    cudaFuncSetAttribute(pre_kernel,  cudaFuncAttributeMaxDynamicSharedMemorySize, SMEM1);
    cudaFuncSetAttribute(attn_kernel, cudaFuncAttributeMaxDynamicSharedMemorySize, SM_TOT);

    pre_kernel<<<704, 512, SMEM1>>>(X, A, Wq, bq, Wk, bk, Wv, bv);
    attn_kernel<<<128, 512, SM_TOT>>>(Wo, bo, out);
}

// round 10
// speedup vs baseline: 1.1854x; 1.0442x over previous
#include <cuda_runtime.h>
#include <cuda_fp16.h>

#define NB 8
#define NN 1024
#define NF 128
#define NH 8

// -------- scratch (device globals; allocation is forbidden) --------
__device__ __half    g_Q[NB*NN*NF];      // [b*N+q][128], pre-scaled by log2e/4
__device__ __half    g_K[NB*NN*NF];      // [b*N+q][128]
__device__ __half    g_V[NB*NN*NF];      // [b][t16=q/16][o(128)][qi(16)]  (16-key tiled)
__device__ unsigned  g_mask[NB*NN*32];   // [b*N+q][word]; bit j of word w = A[..][w*32+j]>0

#define QSCALE 0.3606737602222409f   // log2(e)/4
#define ONES2  0x3C003C00u           // half2(1,1)

// attn smem layout (bytes) — triple-buffered K/V, 2 parity tiles per buffer
#define SM_WOS   0        // Wos[128][136] half      = 34816
#define SM_XS    34816    // Xs[64][136]  half       = 17408
#define SM_MASK  52224    // smask[64][33] u32       = 8448
#define SM_BS    60672    // bs[128] float           = 512
#define SM_KS    61184    // Ks[3][2][32][136] half  = 52224  (8704/tile)
#define SM_VS    113408   // Vs[3][2][128][40] half  = 61440  (10240/tile)
#define SM_TOT   174848

// -------- helpers --------
static __device__ __forceinline__ float rcpf(float x){ float r; asm("rcp.approx.ftz.f32 %0,%1;":"=f"(r):"f"(x)); return r; }
static __device__ __forceinline__ unsigned h2(float a,float b){
    __half2 h = __floats2half2_rn(a,b); return *reinterpret_cast<unsigned*>(&h); }
static __device__ __forceinline__ unsigned hex2(unsigned x){
    unsigned r; asm("ex2.approx.f16x2 %0,%1;":"=r"(r):"r"(x)); return r; }
// expand low 2 bits -> per-half 0xFFFF masks
static __device__ __forceinline__ unsigned mpat(unsigned bits){
    unsigned t = (bits & 3u) * 0x4080u;
    unsigned r; asm("prmt.b32 %0,%1,%2,%3;":"=r"(r):"r"(t),"r"(0u),"r"(0x9988u));
    return r;
}
static __device__ __forceinline__ void mma16816(float c[4], const unsigned a[4], unsigned b0, unsigned b1){
    asm volatile("mma.sync.aligned.m16n8k16.row.col.f32.f16.f16.f32 "
                 "{%0,%1,%2,%3},{%4,%5,%6,%7},{%8,%9},{%0,%1,%2,%3};"
                 : "+f"(c[0]),"+f"(c[1]),"+f"(c[2]),"+f"(c[3])
                 : "r"(a[0]),"r"(a[1]),"r"(a[2]),"r"(a[3]),"r"(b0),"r"(b1));
}
// QK mma with fp16 accumulator (zero-init): d0={rows 0-7 pair}, d1={rows 8-15 pair}
static __device__ __forceinline__ void mma16816h(unsigned &d0, unsigned &d1,
        const unsigned a[4], unsigned b0, unsigned b1){
    asm volatile("mma.sync.aligned.m16n8k16.row.col.f16.f16.f16.f16 "
                 "{%0,%1},{%2,%3,%4,%5},{%6,%7},{%8,%8};"
                 : "=r"(d0),"=r"(d1)
                 : "r"(a[0]),"r"(a[1]),"r"(a[2]),"r"(a[3]),"r"(b0),"r"(b1),"r"(0u));
}
static __device__ __forceinline__ void ldm4(unsigned r[4], unsigned addr){
    asm volatile("ldmatrix.sync.aligned.m8n8.x4.shared.b16 {%0,%1,%2,%3}, [%4];"
        : "=r"(r[0]),"=r"(r[1]),"=r"(r[2]),"=r"(r[3]) : "r"(addr));
}
static __device__ __forceinline__ void cpa16(unsigned dst, const void* src){
    asm volatile("cp.async.cg.shared.global [%0], [%1], 16;" :: "r"(dst), "l"(src) : "memory");
}

// ============ kernel 1: fused mask compaction + Q/K/V projections ============
__global__ __launch_bounds__(512) void pre_kernel(const float* __restrict__ X,
        const float* __restrict__ A,
        const float* __restrict__ Wq, const float* __restrict__ bq,
        const float* __restrict__ Wk, const float* __restrict__ bk,
        const float* __restrict__ Wv, const float* __restrict__ bv){
    int bid = blockIdx.x;
    int tid = threadIdx.x;
    int w = tid >> 5, lane = tid & 31;

    if (bid >= 192){
        int row = (bid - 192) * 16 + w;               // 0..8191 (b*N+q)
        const float* a = A + (size_t)row * NN;
        unsigned myw = 0;
        #pragma unroll
        for (int j = 0; j < 32; ++j){
            unsigned m = __ballot_sync(0xffffffffu, a[j*32 + lane] > 0.0f);
            if (lane == j) myw = m;
        }
        g_mask[(size_t)row * 32 + lane] = myw;
        return;
    }

    extern __shared__ char smem[];
    __half (*Xs)[136] = (__half(*)[136])smem;
    __half (*Ws)[136] = (__half(*)[136])(smem + 34816);
    float*  bs        = (float*)(smem + 69632);

    int mode = bid >> 6;        // 0=Q 1=K 2=V
    int tile = bid & 63;
    const float* Wp = (mode == 0) ? Wq : (mode == 1) ? Wk : Wv;
    const float* bp = (mode == 0) ? bq : (mode == 1) ? bk : bv;
    int row0 = tile * 128;

    for (int i = tid; i < 4096; i += 512){
        int r = i >> 5, c4 = (i & 31) * 4;
        float4 v = *(const float4*)&X[(size_t)(row0 + r)*NF + c4];
        uint2 u; u.x = h2(v.x, v.y); u.y = h2(v.z, v.w);
        *(uint2*)&Xs[r][c4] = u;
        float4 ww = *(const float4*)&Wp[(size_t)r*NF + c4];
        uint2 uw; uw.x = h2(ww.x, ww.y); uw.y = h2(ww.z, ww.w);
        *(uint2*)&Ws[r][c4] = uw;
    }
    if (tid < 128) bs[tid] = bp[tid];
    __syncthreads();

    int qr = lane >> 2, lc = lane & 3, ms = lc * 2;
    int rg = w >> 1, ch = w & 1;

    const unsigned* Ab = (mode == 2) ? (const unsigned*)Ws : (const unsigned*)Xs;
    const unsigned* Bb = (mode == 2) ? (const unsigned*)Xs : (const unsigned*)Ws;

    unsigned a[8][4];
    {
        const unsigned* p = Ab + (16*rg + qr)*68 + lc;
        #pragma unroll
        for (int kt = 0; kt < 8; ++kt){
            a[kt][0] = p[kt*8];
            a[kt][1] = p[kt*8 + 8*68];
            a[kt][2] = p[kt*8 + 4];
            a[kt][3] = p[kt*8 + 8*68 + 4];
        }
    }

    float c[8][4];
    #pragma unroll
    for (int j = 0; j < 8; ++j){ c[j][0]=0.f; c[j][1]=0.f; c[j][2]=0.f; c[j][3]=0.f; }
    #pragma unroll
    for (int j = 0; j < 8; ++j){
        const unsigned* bpq = Bb + (64*ch + 8*j + qr)*68 + lc;
        #pragma unroll
        for (int kt = 0; kt < 8; ++kt)
            mma16816(c[j], a[kt], bpq[kt*8], bpq[kt*8 + 4]);
    }

    int b = row0 >> 10, q0 = row0 & (NN - 1);
    #pragma unroll
    for (int j = 0; j < 8; ++j){
        if (mode == 2){
            int o0 = 16*rg + qr, o1 = o0 + 8;
            int qg = q0 + 64*ch + 8*j + ms;        // global q within batch
            int t16 = qg >> 4, qi = qg & 15;
            float b0 = bs[o0], b1 = bs[o1];
            __half* base = g_V + ((size_t)(b*64 + t16) * 128) * 16;
            *(unsigned*)&base[o0*16 + qi] = h2(c[j][0]+b0, c[j][1]+b0);
            *(unsigned*)&base[o1*16 + qi] = h2(c[j][2]+b1, c[j][3]+b1);
        } else {
            int col = 64*ch + 8*j + ms;
            float b0 = bs[col], b1 = bs[col + 1];
            int r = row0 + 16*rg + qr;
            if (mode == 0){
                *(unsigned*)&g_Q[(size_t)r*NF + col]     = h2((c[j][0]+b0)*QSCALE, (c[j][1]+b1)*QSCALE);
                *(unsigned*)&g_Q[(size_t)(r+8)*NF + col] = h2((c[j][2]+b0)*QSCALE, (c[j][3]+b1)*QSCALE);
            } else {
                *(unsigned*)&g_K[(size_t)r*NF + col]     = h2(c[j][0]+b0, c[j][1]+b1);
                *(unsigned*)&g_K[(size_t)(r+8)*NF + col] = h2(c[j][2]+b0, c[j][3]+b1);
            }
        }
    }
}

// ============ kernel 2: masked flash attention + fused output projection ============
// grid 128 (b, q0-tile of 64), 512 threads: warp = (par, head); h = wid&7, par = wid>>3
// warp processes ALL 64 queries of its head over key tiles 2*it+par (key-parity split);
// partial (o, lsum) combined via smem. K/V triple-buffered (2 parity tiles per stage).
__global__ __launch_bounds__(512) void attn_kernel(const float* __restrict__ Wo,
        const float* __restrict__ bo, float* __restrict__ out){
    extern __shared__ char smem[];
    __half   (*Wos)[136]  = (__half(*)[136])(smem + SM_WOS);
    __half   (*Xs)[136]   = (__half(*)[136])(smem + SM_XS);
    unsigned (*smask)[33] = (unsigned(*)[33])(smem + SM_MASK);
    float*    bs          = (float*)(smem + SM_BS);
    const unsigned smem_u = (unsigned)__cvta_generic_to_shared(smem);

    int tid = threadIdx.x;
    int b  = blockIdx.x >> 4;
    int q0 = (blockIdx.x & 15) * 64;
    int wid = tid >> 5, lane = tid & 31;
    int h = wid & 7, par = wid >> 3;

    // stage Wo (fp32->fp16), bias, mask
    for (int i = tid; i < 4096; i += 512){
        int r = i >> 5, c4 = (i & 31) * 4;
        float4 v = *(const float4*)&Wo[(size_t)r*NF + c4];
        uint2 u; u.x = h2(v.x, v.y); u.y = h2(v.z, v.w);
        *(uint2*)&Wos[r][c4] = u;
    }
    if (tid < 128) bs[tid] = bo[tid];
    for (int i = tid; i < 2048; i += 512){
        int r = i >> 5, ww = i & 31;
        smask[r][ww] = g_mask[(size_t)((b<<10) + q0 + r)*32 + ww];
    }

    int qr = lane >> 2;
    int lc = lane & 3;
    int ms = lc * 2;

    // Q fragments: all 4 (64 query rows) for this head
    unsigned a[4][4];
    #pragma unroll
    for (int f=0; f<4; ++f){
        const __half* Qp = g_Q + (((size_t)((b<<10) + q0 + f*16 + qr)) << 7) + h*16;
        a[f][0] = *(const unsigned*)(Qp + ms);
        a[f][2] = *(const unsigned*)(Qp + ms + 8);
        const __half* Qp8 = Qp + (8 << 7);
        a[f][1] = *(const unsigned*)(Qp8 + ms);
        a[f][3] = *(const unsigned*)(Qp8 + ms + 8);
    }

    float o[4][2][4];
    float lsum[4][4];
    #pragma unroll
    for (int f=0;f<4;++f){
        #pragma unroll
        for (int j=0;j<4;++j) lsum[f][j]=0.f;
        #pragma unroll
        for (int t=0;t<2;++t){ o[f][t][0]=0.f;o[f][t][1]=0.f;o[f][t][2]=0.f;o[f][t][3]=0.f; }
    }

    // per-thread staging descriptors: each superiter stages 2 parity tiles (64 keys)
    const int krow = tid >> 4, kch = tid & 15;               // K: 32 rows x 16 chunks
    const int vo = tid >> 2, vc = tid & 3;                   // V: 128 rows x 4 chunks
    const unsigned kdst = smem_u + SM_KS + (krow*136 + kch*8)*2;
    const unsigned vdst = smem_u + SM_VS + (vo*40 + vc*8)*2;
    const __half* ksrc0 = g_K + ((size_t)(b<<10) + krow)*NF + kch*8;
    const __half* vsrc0 = g_V + ((size_t)(b*64 + (vc>>1))*128 + vo)*16 + (vc&1)*8;

    #define STAGE(sit, bf) do { \
        const __half* ks = ksrc0 + (size_t)(sit)*64*NF; \
        cpa16(kdst + (bf)*17408,        ks); \
        cpa16(kdst + (bf)*17408 + 8704, ks + 32*NF); \
        const __half* vs = vsrc0 + (size_t)(sit)*4*2048; \
        cpa16(vdst + (bf)*20480,         vs); \
        cpa16(vdst + (bf)*20480 + 10240, vs + 2*2048); \
        asm volatile("cp.async.commit_group;" ::: "memory"); \
    } while(0)

    STAGE(0, 0);
    STAGE(1, 1);

    // per-thread ldmatrix address offsets (within this warp's parity tile)
    const unsigned kfrag = smem_u + SM_KS + par*8704 +
        ((((lane>>4)&1)*8 + (lane&7))*136 + h*16 + ((lane>>3)&1)*8)*2;
    const unsigned vfrag = smem_u + SM_VS + par*10240 +
        ((h*16 + ((lane>>4)&1)*8 + (lane&7))*40 + ((lane>>3)&1)*8)*2;

    int buf = 0;
    for (int it = 0; it < 16; ++it){
        if (it < 15) asm volatile("cp.async.wait_group 1;" ::: "memory");
        else         asm volatile("cp.async.wait_group 0;" ::: "memory");
        __syncthreads();

        if (it + 2 <= 15){
            int nbuf = buf + 2; if (nbuf >= 3) nbuf -= 3;
            STAGE(it + 2, nbuf);
        }

        unsigned kb[2][4], vb[2][4];
        unsigned kf = kfrag + buf*17408;
        unsigned vf = vfrag + buf*20480;
        ldm4(kb[0], kf);
        ldm4(kb[1], kf + 16*136*2);
        ldm4(vb[0], vf);
        ldm4(vb[1], vf + 32);

        int mw = 2*it + par;     // mask word = key tile index
        #pragma unroll
        for (int sub = 0; sub < 2; ++sub){
            int sbms = (sub << 4) + ms;
            #pragma unroll
            for (int f=0; f<4; ++f){
                unsigned d0, d1, d2, d3;
                mma16816h(d0, d1, a[f], kb[sub][0], kb[sub][1]);
                mma16816h(d2, d3, a[f], kb[sub][2], kb[sub][3]);
                unsigned mlo = smask[f*16 + qr][mw]     >> sbms;
                unsigned mhi = smask[f*16 + 8 + qr][mw] >> sbms;
                unsigned ap[4];
                ap[0] = hex2(d0) & mpat(mlo);
                ap[1] = hex2(d1) & mpat(mhi);
                ap[2] = hex2(d2) & mpat(mlo >> 8);
                ap[3] = hex2(d3) & mpat(mhi >> 8);
                mma16816(o[f][0], ap, vb[sub][0], vb[sub][1]);
                mma16816(o[f][1], ap, vb[sub][2], vb[sub][3]);
                mma16816(lsum[f], ap, ONES2, ONES2);
            }
        }
        ++buf; if (buf >= 3) buf = 0;
    }

    // ---- combine parity partials via smem scratch (reuse K/V region) ----
    __syncthreads();
    float* osum  = (float*)(smem + SM_KS);                 // [64][132] f32
    float* lsums = (float*)(smem + SM_KS + 64*132*4);      // [64][8]  f32
    if (par == 0){
        #pragma unroll
        for (int f=0; f<4; ++f){
            int r0 = f*16 + qr, r1 = r0 + 8;
            #pragma unroll
            for (int t=0; t<2; ++t){
                *(float2*)&osum[r0*132 + h*16 + t*8 + ms] = make_float2(o[f][t][0], o[f][t][1]);
                *(float2*)&osum[r1*132 + h*16 + t*8 + ms] = make_float2(o[f][t][2], o[f][t][3]);
            }
            if (lc == 0){
                lsums[r0*8 + h] = lsum[f][0];
                lsums[r1*8 + h] = lsum[f][2];
            }
        }
    }
    __syncthreads();
    if (par == 1){
        #pragma unroll
        for (int f=0; f<4; ++f){
            int r0 = f*16 + qr, r1 = r0 + 8;
            float inv0 = rcpf(lsum[f][0] + lsums[r0*8 + h]);
            float inv1 = rcpf(lsum[f][2] + lsums[r1*8 + h]);
            #pragma unroll
            for (int t=0; t<2; ++t){
                float2 p0 = *(float2*)&osum[r0*132 + h*16 + t*8 + ms];
                float2 p1 = *(float2*)&osum[r1*132 + h*16 + t*8 + ms];
                *(unsigned*)&Xs[r0][h*16 + t*8 + ms] = h2((o[f][t][0]+p0.x)*inv0, (o[f][t][1]+p0.y)*inv0);
                *(unsigned*)&Xs[r1][h*16 + t*8 + ms] = h2((o[f][t][2]+p1.x)*inv1, (o[f][t][3]+p1.y)*inv1);
            }
        }
    }
    __syncthreads();

    // ---- fused output projection: out(64x128) = Xs @ Wos^T + bo ----
    int rg = wid >> 2, cq = wid & 3;
    unsigned a2[8][4];
    {
        const unsigned* p = (const unsigned*)Xs + (16*rg + qr)*68 + lc;
        #pragma unroll
        for (int kt = 0; kt < 8; ++kt){
            a2[kt][0] = p[kt*8];
            a2[kt][1] = p[kt*8 + 8*68];
            a2[kt][2] = p[kt*8 + 4];
            a2[kt][3] = p[kt*8 + 8*68 + 4];
        }
    }
    #pragma unroll
    for (int j = 0; j < 4; ++j){
        float c[4] = {0.f,0.f,0.f,0.f};
        const unsigned* bp = (const unsigned*)Wos + (32*cq + 8*j + qr)*68 + lc;
        #pragma unroll
        for (int kt = 0; kt < 8; ++kt)
            mma16816(c, a2[kt], bp[kt*8], bp[kt*8 + 4]);
        int col = 32*cq + 8*j + ms;
        float b0 = bs[col], b1 = bs[col + 1];
        int r = (b<<10) + q0 + 16*rg + qr;
        *(float2*)&out[(size_t)r*NF + col]     = make_float2(c[0]+b0, c[1]+b1);
        *(float2*)&out[(size_t)(r+8)*NF + col] = make_float2(c[2]+b0, c[3]+b1);
    }
}

// -------- launcher --------
extern "C" void kernel_launch(void* const* d_in, const int* in_sizes, int n_in,
                              void* d_out, int out_size){
    const float* X  = (const float*)d_in[0];
    const float* A  = (const float*)d_in[1];
    const float* Wq = (const float*)d_in[2];
    const float* bq = (const float*)d_in[3];
    const float* Wk = (const float*)d_in[4];
    const float* bk = (const float*)d_in[5];
    const float* Wv = (const float*)d_in[6];
    const float* bv = (const float*)d_in[7];
    const float* Wo = (const float*)d_in[8];
    const float* bo = (const float*)d_in[9];
    float* out = (float*)d_out;

    const int SMEM1 = 70144;
    cudaFuncSetAttribute(pre_kernel,  cudaFuncAttributeMaxDynamicSharedMemorySize, SMEM1);
    cudaFuncSetAttribute(attn_kernel, cudaFuncAttributeMaxDynamicSharedMemorySize, SM_TOT);

    pre_kernel<<<704, 512, SMEM1>>>(X, A, Wq, bq, Wk, bk, Wv, bv);
    attn_kernel<<<128, 512, SM_TOT>>>(Wo, bo, out);
}

// round 11
// speedup vs baseline: 1.3985x; 1.1798x over previous
#include <cuda_runtime.h>
#include <cuda_fp16.h>

#define NB 8
#define NN 1024
#define NF 128
#define NH 8

// -------- scratch (device globals; allocation is forbidden) --------
__device__ __half    g_Q[NB*NN*NF];      // [b*N+q][128], pre-scaled by log2e/4
// K/V in mma-fragment order: [b][kt(64)][h(8)][lane(32)][slot(4)] u32
// K slots: (rowlo,dlo),(rowlo,dhi),(rowhi,dlo),(rowhi,dhi)  row=key qr, d=ms pair
// V slots: (olo,klo),(olo,khi),(ohi,klo),(ohi,khi)          o=qr, k=ms pair
__device__ unsigned  g_K[NB*NN*64];
__device__ unsigned  g_V[NB*NN*64];
__device__ unsigned  g_mask[NB*NN*32];   // [b*N+q][word]; bit j of word w = A[..][w*32+j]>0

#define QSCALE 0.3606737602222409f   // log2(e)/4
#define ONES2  0x3C003C00u           // half2(1,1)

// attn smem layout (bytes) — no K/V staging anymore
#define SM_WOS   0        // Wos[128][136] half   = 34816
#define SM_XS    34816    // Xs[64][136]  half    = 17408
#define SM_MASK  52224    // smask[64][33] u32    = 8448
#define SM_BS    60672    // bs[128] float        = 512
#define SM_SCR   61184    // osum[64][132] f32 = 33792 ; lsums[64][8] f32 = 2048
#define SM_TOT   97024

// -------- helpers --------
static __device__ __forceinline__ float rcpf(float x){ float r; asm("rcp.approx.ftz.f32 %0,%1;":"=f"(r):"f"(x)); return r; }
static __device__ __forceinline__ unsigned h2(float a,float b){
    __half2 h = __floats2half2_rn(a,b); return *reinterpret_cast<unsigned*>(&h); }
static __device__ __forceinline__ unsigned hex2(unsigned x){
    unsigned r; asm("ex2.approx.f16x2 %0,%1;":"=r"(r):"r"(x)); return r; }
// expand low 2 bits -> per-half 0xFFFF masks
static __device__ __forceinline__ unsigned mpat(unsigned bits){
    unsigned t = (bits & 3u) * 0x4080u;
    unsigned r; asm("prmt.b32 %0,%1,%2,%3;":"=r"(r):"r"(t),"r"(0u),"r"(0x9988u));
    return r;
}
static __device__ __forceinline__ void mma16816(float c[4], const unsigned a[4], unsigned b0, unsigned b1){
    asm volatile("mma.sync.aligned.m16n8k16.row.col.f32.f16.f16.f32 "
                 "{%0,%1,%2,%3},{%4,%5,%6,%7},{%8,%9},{%0,%1,%2,%3};"
                 : "+f"(c[0]),"+f"(c[1]),"+f"(c[2]),"+f"(c[3])
                 : "r"(a[0]),"r"(a[1]),"r"(a[2]),"r"(a[3]),"r"(b0),"r"(b1));
}
// QK mma with fp16 accumulator (zero-init): d0={rows 0-7 pair}, d1={rows 8-15 pair}
static __device__ __forceinline__ void mma16816h(unsigned &d0, unsigned &d1,
        const unsigned a[4], unsigned b0, unsigned b1){
    asm volatile("mma.sync.aligned.m16n8k16.row.col.f16.f16.f16.f16 "
                 "{%0,%1},{%2,%3,%4,%5},{%6,%7},{%8,%8};"
                 : "=r"(d0),"=r"(d1)
                 : "r"(a[0]),"r"(a[1]),"r"(a[2]),"r"(a[3]),"r"(b0),"r"(b1),"r"(0u));
}

// ============ kernel 1: fused mask compaction + Q/K/V projections ============
__global__ __launch_bounds__(512) void pre_kernel(const float* __restrict__ X,
        const float* __restrict__ A,
        const float* __restrict__ Wq, const float* __restrict__ bq,
        const float* __restrict__ Wk, const float* __restrict__ bk,
        const float* __restrict__ Wv, const float* __restrict__ bv){
    int bid = blockIdx.x;
    int tid = threadIdx.x;
    int w = tid >> 5, lane = tid & 31;

    if (bid >= 192){
        int row = (bid - 192) * 16 + w;               // 0..8191 (b*N+q)
        const float* a = A + (size_t)row * NN;
        unsigned myw = 0;
        #pragma unroll
        for (int j = 0; j < 32; ++j){
            unsigned m = __ballot_sync(0xffffffffu, a[j*32 + lane] > 0.0f);
            if (lane == j) myw = m;
        }
        g_mask[(size_t)row * 32 + lane] = myw;
        return;
    }

    extern __shared__ char smem[];
    __half (*Xs)[136] = (__half(*)[136])smem;
    __half (*Ws)[136] = (__half(*)[136])(smem + 34816);
    float*  bs        = (float*)(smem + 69632);

    int mode = bid >> 6;        // 0=Q 1=K 2=V
    int tile = bid & 63;
    const float* Wp = (mode == 0) ? Wq : (mode == 1) ? Wk : Wv;
    const float* bp = (mode == 0) ? bq : (mode == 1) ? bk : bv;
    int row0 = tile * 128;

    for (int i = tid; i < 4096; i += 512){
        int r = i >> 5, c4 = (i & 31) * 4;
        float4 v = *(const float4*)&X[(size_t)(row0 + r)*NF + c4];
        uint2 u; u.x = h2(v.x, v.y); u.y = h2(v.z, v.w);
        *(uint2*)&Xs[r][c4] = u;
        float4 ww = *(const float4*)&Wp[(size_t)r*NF + c4];
        uint2 uw; uw.x = h2(ww.x, ww.y); uw.y = h2(ww.z, ww.w);
        *(uint2*)&Ws[r][c4] = uw;
    }
    if (tid < 128) bs[tid] = bp[tid];
    __syncthreads();

    int qr = lane >> 2, lc = lane & 3, ms = lc * 2;
    int rg = w >> 1, ch = w & 1;

    const unsigned* Ab = (mode == 2) ? (const unsigned*)Ws : (const unsigned*)Xs;
    const unsigned* Bb = (mode == 2) ? (const unsigned*)Xs : (const unsigned*)Ws;

    unsigned a[8][4];
    {
        const unsigned* p = Ab + (16*rg + qr)*68 + lc;
        #pragma unroll
        for (int kt = 0; kt < 8; ++kt){
            a[kt][0] = p[kt*8];
            a[kt][1] = p[kt*8 + 8*68];
            a[kt][2] = p[kt*8 + 4];
            a[kt][3] = p[kt*8 + 8*68 + 4];
        }
    }

    float c[8][4];
    #pragma unroll
    for (int j = 0; j < 8; ++j){ c[j][0]=0.f; c[j][1]=0.f; c[j][2]=0.f; c[j][3]=0.f; }
    #pragma unroll
    for (int j = 0; j < 8; ++j){
        const unsigned* bpq = Bb + (64*ch + 8*j + qr)*68 + lc;
        #pragma unroll
        for (int kt = 0; kt < 8; ++kt)
            mma16816(c[j], a[kt], bpq[kt*8], bpq[kt*8 + 4]);
    }

    int b = row0 >> 10, q0 = row0 & (NN - 1);
    #pragma unroll
    for (int j = 0; j < 8; ++j){
        if (mode == 2){
            // V fragment store: o0 = 16rg+qr (head rg, o-lo qr), o1 = o0+8
            int o0 = 16*rg + qr, o1 = o0 + 8;
            int kt = (q0 >> 4) + 4*ch + (j >> 1);
            float bo0 = bs[o0], bo1 = bs[o1];
            unsigned* basep = g_V + ((((b<<6) + kt)<<3) + rg)*128 + (qr*4 + (ms>>1))*4;
            basep[(j&1)]     = h2(c[j][0]+bo0, c[j][1]+bo0);
            basep[2 + (j&1)] = h2(c[j][2]+bo1, c[j][3]+bo1);
        } else {
            int col = 64*ch + 8*j + ms;
            float b0 = bs[col], b1 = bs[col + 1];
            if (mode == 0){
                int r = row0 + 16*rg + qr;
                *(unsigned*)&g_Q[(size_t)r*NF + col]     = h2((c[j][0]+b0)*QSCALE, (c[j][1]+b1)*QSCALE);
                *(unsigned*)&g_Q[(size_t)(r+8)*NF + col] = h2((c[j][2]+b0)*QSCALE, (c[j][3]+b1)*QSCALE);
            } else {
                // K fragment store: key rows r=q, head hh, d-pair within head
                int hh = 4*ch + (j >> 1);
                int kt = (q0 >> 4) + rg;
                unsigned* basep = g_K + ((((b<<6) + kt)<<3) + hh)*128 + (qr*4 + (ms>>1))*4;
                basep[(j&1)]     = h2(c[j][0]+b0, c[j][1]+b1);
                basep[2 + (j&1)] = h2(c[j][2]+b0, c[j][3]+b1);
            }
        }
    }
}

// ============ kernel 2: masked flash attention + fused output projection ============
// grid 128 (b, q0-tile of 64), 512 threads: warp = (par, head)
// warp processes all 64 queries of its head over key tiles kt = 2t+par (t=0..31).
// K/V fetched straight from gmem in fragment order: 1 LDG.128 each per tile,
// depth-2 register rotation. NO mainloop barriers or smem staging.
__global__ __launch_bounds__(512) void attn_kernel(const float* __restrict__ Wo,
        const float* __restrict__ bo, float* __restrict__ out){
    extern __shared__ char smem[];
    __half   (*Wos)[136]  = (__half(*)[136])(smem + SM_WOS);
    __half   (*Xs)[136]   = (__half(*)[136])(smem + SM_XS);
    unsigned (*smask)[33] = (unsigned(*)[33])(smem + SM_MASK);
    float*    bs          = (float*)(smem + SM_BS);

    int tid = threadIdx.x;
    int b  = blockIdx.x >> 4;
    int q0 = (blockIdx.x & 15) * 64;
    int wid = tid >> 5, lane = tid & 31;
    int h = wid & 7, par = wid >> 3;

    // stage Wo (fp32->fp16), bias, mask
    for (int i = tid; i < 4096; i += 512){
        int r = i >> 5, c4 = (i & 31) * 4;
        float4 v = *(const float4*)&Wo[(size_t)r*NF + c4];
        uint2 u; u.x = h2(v.x, v.y); u.y = h2(v.z, v.w);
        *(uint2*)&Wos[r][c4] = u;
    }
    if (tid < 128) bs[tid] = bo[tid];
    for (int i = tid; i < 2048; i += 512){
        int r = i >> 5, ww = i & 31;
        smask[r][ww] = g_mask[(size_t)((b<<10) + q0 + r)*32 + ww];
    }

    int qr = lane >> 2;
    int lc = lane & 3;
    int ms = lc * 2;
    const int sh = par*16 + ms;    // constant mask shift for this thread

    // Q fragments: all 4 (64 query rows) for this head
    unsigned a[4][4];
    #pragma unroll
    for (int f=0; f<4; ++f){
        const __half* Qp = g_Q + (((size_t)((b<<10) + q0 + f*16 + qr)) << 7) + h*16;
        a[f][0] = *(const unsigned*)(Qp + ms);
        a[f][2] = *(const unsigned*)(Qp + ms + 8);
        const __half* Qp8 = Qp + (8 << 7);
        a[f][1] = *(const unsigned*)(Qp8 + ms);
        a[f][3] = *(const unsigned*)(Qp8 + ms + 8);
    }

    float o[4][2][4];
    float lsum[4][4];
    #pragma unroll
    for (int f=0;f<4;++f){
        #pragma unroll
        for (int j=0;j<4;++j) lsum[f][j]=0.f;
        #pragma unroll
        for (int t=0;t<2;++t){ o[f][t][0]=0.f;o[f][t][1]=0.f;o[f][t][2]=0.f;o[f][t][3]=0.f; }
    }

    __syncthreads();   // smask visible

    // fragment pointers: tile kt = 2t+par ; stride per t = 2 tiles = 512 uint4
    const uint4* Kp = ((const uint4*)g_K) + ((((b<<6) + par)<<3) + h)*32 + lane;
    const uint4* Vp = ((const uint4*)g_V) + ((((b<<6) + par)<<3) + h)*32 + lane;

    uint4 ka = Kp[0],   va = Vp[0];
    uint4 kb = Kp[512], vb = Vp[512];

    for (int t = 0; t < 32; ++t){
        uint4 kn, vn;
        if (t < 30){ kn = Kp[(size_t)(t+2)*512]; vn = Vp[(size_t)(t+2)*512]; }
        else       { kn = ka; vn = va; }

        #pragma unroll
        for (int f=0; f<4; ++f){
            unsigned d0, d1, d2, d3;
            mma16816h(d0, d1, a[f], ka.x, ka.y);
            mma16816h(d2, d3, a[f], ka.z, ka.w);
            unsigned mlo = smask[f*16 + qr][t]     >> sh;
            unsigned mhi = smask[f*16 + 8 + qr][t] >> sh;
            unsigned ap[4];
            ap[0] = hex2(d0) & mpat(mlo);
            ap[1] = hex2(d1) & mpat(mhi);
            ap[2] = hex2(d2) & mpat(mlo >> 8);
            ap[3] = hex2(d3) & mpat(mhi >> 8);
            mma16816(o[f][0], ap, va.x, va.y);
            mma16816(o[f][1], ap, va.z, va.w);
            mma16816(lsum[f], ap, ONES2, ONES2);
        }
        ka = kb; va = vb; kb = kn; vb = vn;
    }

    // ---- combine parity partials via smem scratch ----
    __syncthreads();
    float* osum  = (float*)(smem + SM_SCR);                 // [64][132] f32
    float* lsums = (float*)(smem + SM_SCR + 64*132*4);      // [64][8]  f32
    if (par == 0){
        #pragma unroll
        for (int f=0; f<4; ++f){
            int r0 = f*16 + qr, r1 = r0 + 8;
            #pragma unroll
            for (int t=0; t<2; ++t){
                *(float2*)&osum[r0*132 + h*16 + t*8 + ms] = make_float2(o[f][t][0], o[f][t][1]);
                *(float2*)&osum[r1*132 + h*16 + t*8 + ms] = make_float2(o[f][t][2], o[f][t][3]);
            }
            if (lc == 0){
                lsums[r0*8 + h] = lsum[f][0];
                lsums[r1*8 + h] = lsum[f][2];
            }
        }
    }
    __syncthreads();
    if (par == 1){
        #pragma unroll
        for (int f=0; f<4; ++f){
            int r0 = f*16 + qr, r1 = r0 + 8;
            float inv0 = rcpf(lsum[f][0] + lsums[r0*8 + h]);
            float inv1 = rcpf(lsum[f][2] + lsums[r1*8 + h]);
            #pragma unroll
            for (int t=0; t<2; ++t){
                float2 p0 = *(float2*)&osum[r0*132 + h*16 + t*8 + ms];
                float2 p1 = *(float2*)&osum[r1*132 + h*16 + t*8 + ms];
                *(unsigned*)&Xs[r0][h*16 + t*8 + ms] = h2((o[f][t][0]+p0.x)*inv0, (o[f][t][1]+p0.y)*inv0);
                *(unsigned*)&Xs[r1][h*16 + t*8 + ms] = h2((o[f][t][2]+p1.x)*inv1, (o[f][t][3]+p1.y)*inv1);
            }
        }
    }
    __syncthreads();

    // ---- fused output projection: out(64x128) = Xs @ Wos^T + bo ----
    int rg = wid >> 2, cq = wid & 3;
    unsigned a2[8][4];
    {
        const unsigned* p = (const unsigned*)Xs + (16*rg + qr)*68 + lc;
        #pragma unroll
        for (int kt = 0; kt < 8; ++kt){
            a2[kt][0] = p[kt*8];
            a2[kt][1] = p[kt*8 + 8*68];
            a2[kt][2] = p[kt*8 + 4];
            a2[kt][3] = p[kt*8 + 8*68 + 4];
        }
    }
    #pragma unroll
    for (int j = 0; j < 4; ++j){
        float c[4] = {0.f,0.f,0.f,0.f};
        const unsigned* bp = (const unsigned*)Wos + (32*cq + 8*j + qr)*68 + lc;
        #pragma unroll
        for (int kt = 0; kt < 8; ++kt)
            mma16816(c, a2[kt], bp[kt*8], bp[kt*8 + 4]);
        int col = 32*cq + 8*j + ms;
        float b0 = bs[col], b1 = bs[col + 1];
        int r = (b<<10) + q0 + 16*rg + qr;
        *(float2*)&out[(size_t)r*NF + col]     = make_float2(c[0]+b0, c[1]+b1);
        *(float2*)&out[(size_t)(r+8)*NF + col] = make_float2(c[2]+b0, c[3]+b1);
    }
}

// -------- launcher --------
extern "C" void kernel_launch(void* const* d_in, const int* in_sizes, int n_in,
                              void* d_out, int out_size){
    const float* X  = (const float*)d_in[0];
    const float* A  = (const float*)d_in[1];
    const float* Wq = (const float*)d_in[2];
    const float* bq = (const float*)d_in[3];
    const float* Wk = (const float*)d_in[4];
    const float* bk = (const float*)d_in[5];
    const float* Wv = (const float*)d_in[6];
    const float* bv = (const float*)d_in[7];
    const float* Wo = (const float*)d_in[8];
    const float* bo = (const float*)d_in[9];
    float* out = (float*)d_out;

    const int SMEM1 = 70144;
    cudaFuncSetAttribute(pre_kernel,  cudaFuncAttributeMaxDynamicSharedMemorySize, SMEM1);
    cudaFuncSetAttribute(attn_kernel, cudaFuncAttributeMaxDynamicSharedMemorySize, SM_TOT);

    pre_kernel<<<704, 512, SMEM1>>>(X, A, Wq, bq, Wk, bk, Wv, bv);
    attn_kernel<<<128, 512, SM_TOT>>>(Wo, bo, out);
}

// round 12
// speedup vs baseline: 1.4354x; 1.0264x over previous
#include <cuda_runtime.h>
#include <cuda_fp16.h>

#define NB 8
#define NN 1024
#define NF 128
#define NH 8

// -------- scratch (device globals; allocation is forbidden) --------
__device__ __half    g_Q[NB*NN*NF];      // [b*N+q][128], pre-scaled by log2e/4
// K/V in mma-fragment order: [b][kt(64)][h(8)][lane(32)][slot(4)] u32
__device__ unsigned  g_K[NB*NN*64];
__device__ unsigned  g_V[NB*NN*64];
// expanded masks in fragment order: [mb=b*16+qt][kt(64)][fp(2)][lane(32)] uint4
// uint4 = (f=2fp: x=klo bytes, y=khi bytes ; f=2fp+1: z,w). byte = 0x3C keep / 0x00 mask
// x bytes: [rowlo k2lc, rowlo k2lc+1, rowhi k2lc, rowhi k2lc+1]
__device__ uint4     g_emask[NB*16*64*2*32];

#define QSCALE 0.3606737602222409f   // log2(e)/4
#define ONES2  0x3C003C00u           // half2(1,1)

// attn smem layout (bytes)
#define SM_WOS   0        // Wos[128][136] half   = 34816
#define SM_XS    34816    // Xs[64][136]  half    = 17408
#define SM_BS    52224    // bs[128] float        = 512
#define SM_SCR   52736    // osum[64][132] f32 = 33792 ; lsums[64][8] f32 = 2048
#define SM_TOT   88576

// -------- helpers --------
static __device__ __forceinline__ float rcpf(float x){ float r; asm("rcp.approx.ftz.f32 %0,%1;":"=f"(r):"f"(x)); return r; }
static __device__ __forceinline__ unsigned h2(float a,float b){
    __half2 h = __floats2half2_rn(a,b); return *reinterpret_cast<unsigned*>(&h); }
static __device__ __forceinline__ unsigned hex2(unsigned x){
    unsigned r; asm("ex2.approx.f16x2 %0,%1;":"=r"(r):"r"(x)); return r; }
static __device__ __forceinline__ unsigned hmul2(unsigned x, unsigned y){
    unsigned r; asm("mul.f16x2 %0,%1,%2;":"=r"(r):"r"(x),"r"(y)); return r; }
static __device__ __forceinline__ unsigned prmtc(unsigned a, unsigned ctrl){
    unsigned r; asm("prmt.b32 %0,%1,%2,%3;":"=r"(r):"r"(a),"r"(0u),"r"(ctrl)); return r; }
static __device__ __forceinline__ void mma16816(float c[4], const unsigned a[4], unsigned b0, unsigned b1){
    asm volatile("mma.sync.aligned.m16n8k16.row.col.f32.f16.f16.f32 "
                 "{%0,%1,%2,%3},{%4,%5,%6,%7},{%8,%9},{%0,%1,%2,%3};"
                 : "+f"(c[0]),"+f"(c[1]),"+f"(c[2]),"+f"(c[3])
                 : "r"(a[0]),"r"(a[1]),"r"(a[2]),"r"(a[3]),"r"(b0),"r"(b1));
}
static __device__ __forceinline__ void mma16816h(unsigned &d0, unsigned &d1,
        const unsigned a[4], unsigned b0, unsigned b1){
    asm volatile("mma.sync.aligned.m16n8k16.row.col.f16.f16.f16.f16 "
                 "{%0,%1},{%2,%3,%4,%5},{%6,%7},{%8,%8};"
                 : "=r"(d0),"=r"(d1)
                 : "r"(a[0]),"r"(a[1]),"r"(a[2]),"r"(a[3]),"r"(b0),"r"(b1),"r"(0u));
}

// ============ kernel 1: fused mask compaction+expansion + Q/K/V projections ============
// blocks 0..191: GEMM (mode = bid/64: 0=Q,1=K,2=V frag), 128x128 tile
// blocks 192..319: mask ballot + fragment-order fp16-byte expansion; block = (b, qt)
__global__ __launch_bounds__(512) void pre_kernel(const float* __restrict__ X,
        const float* __restrict__ A,
        const float* __restrict__ Wq, const float* __restrict__ bq,
        const float* __restrict__ Wk, const float* __restrict__ bk,
        const float* __restrict__ Wv, const float* __restrict__ bv){
    int bid = blockIdx.x;
    int tid = threadIdx.x;
    int w = tid >> 5, lane = tid & 31;
    extern __shared__ char smem[];

    if (bid >= 192){
        // ---- mask block: (b, qt) covers 64 q-rows x 1024 keys ----
        int mb = bid - 192;                // 0..127
        int b = mb >> 4, qt = mb & 15;
        unsigned (*sb)[33] = (unsigned(*)[33])smem;   // ballots [64][33]

        // ballot phase: warp w handles rows w, w+16, w+32, w+48
        #pragma unroll
        for (int rnd = 0; rnd < 4; ++rnd){
            int rr = rnd*16 + w;
            const float* a = A + ((size_t)((b<<10) + (qt<<6) + rr))*NN;
            unsigned myw = 0;
            #pragma unroll
            for (int j = 0; j < 32; ++j){
                unsigned m = __ballot_sync(0xffffffffu, a[j*32 + lane] > 0.0f);
                if (lane == j) myw = m;
            }
            sb[rr][lane] = myw;
        }
        __syncthreads();

        // expansion phase: each thread writes 8 uint4 (coalesced STG.128)
        #pragma unroll
        for (int p = 0; p < 8; ++p){
            int idx = p*512 + tid;
            int kt = idx >> 6, fp = (idx >> 5) & 1, ln = idx & 31;
            int qr2 = ln >> 2, lc2 = ln & 3;
            int s = ((kt & 1) << 4) + 2*lc2;
            int col = kt >> 1;
            uint4 ev;
            {   // f = 2*fp : rows fp*32 + qr2 (+8)
                unsigned wl = sb[fp*32 + qr2][col];
                unsigned wh = sb[fp*32 + 8 + qr2][col];
                unsigned blo = (wl >> s) & 3u, bhi = (wh >> s) & 3u;
                unsigned m = blo*0x4080u | ((bhi*0x4080u) << 16);
                ev.x = prmtc(m, 0xBA98u) & 0x3C3C3C3Cu;
                blo = (wl >> (s+8)) & 3u; bhi = (wh >> (s+8)) & 3u;
                m = blo*0x4080u | ((bhi*0x4080u) << 16);
                ev.y = prmtc(m, 0xBA98u) & 0x3C3C3C3Cu;
            }
            {   // f = 2*fp+1 : rows fp*32 + 16 + qr2 (+8)
                unsigned wl = sb[fp*32 + 16 + qr2][col];
                unsigned wh = sb[fp*32 + 24 + qr2][col];
                unsigned blo = (wl >> s) & 3u, bhi = (wh >> s) & 3u;
                unsigned m = blo*0x4080u | ((bhi*0x4080u) << 16);
                ev.z = prmtc(m, 0xBA98u) & 0x3C3C3C3Cu;
                blo = (wl >> (s+8)) & 3u; bhi = (wh >> (s+8)) & 3u;
                m = blo*0x4080u | ((bhi*0x4080u) << 16);
                ev.w = prmtc(m, 0xBA98u) & 0x3C3C3C3Cu;
            }
            g_emask[((size_t)(mb*64 + kt)*2 + fp)*32 + ln] = ev;
        }
        return;
    }

    // ---- GEMM part (unchanged from R11) ----
    __half (*Xs)[136] = (__half(*)[136])smem;
    __half (*Ws)[136] = (__half(*)[136])(smem + 34816);
    float*  bs        = (float*)(smem + 69632);

    int mode = bid >> 6;        // 0=Q 1=K 2=V
    int tile = bid & 63;
    const float* Wp = (mode == 0) ? Wq : (mode == 1) ? Wk : Wv;
    const float* bp = (mode == 0) ? bq : (mode == 1) ? bk : bv;
    int row0 = tile * 128;

    for (int i = tid; i < 4096; i += 512){
        int r = i >> 5, c4 = (i & 31) * 4;
        float4 v = *(const float4*)&X[(size_t)(row0 + r)*NF + c4];
        uint2 u; u.x = h2(v.x, v.y); u.y = h2(v.z, v.w);
        *(uint2*)&Xs[r][c4] = u;
        float4 ww = *(const float4*)&Wp[(size_t)r*NF + c4];
        uint2 uw; uw.x = h2(ww.x, ww.y); uw.y = h2(ww.z, ww.w);
        *(uint2*)&Ws[r][c4] = uw;
    }
    if (tid < 128) bs[tid] = bp[tid];
    __syncthreads();

    int qr = lane >> 2, lc = lane & 3, ms = lc * 2;
    int rg = w >> 1, ch = w & 1;

    const unsigned* Ab = (mode == 2) ? (const unsigned*)Ws : (const unsigned*)Xs;
    const unsigned* Bb = (mode == 2) ? (const unsigned*)Xs : (const unsigned*)Ws;

    unsigned a[8][4];
    {
        const unsigned* p = Ab + (16*rg + qr)*68 + lc;
        #pragma unroll
        for (int kt = 0; kt < 8; ++kt){
            a[kt][0] = p[kt*8];
            a[kt][1] = p[kt*8 + 8*68];
            a[kt][2] = p[kt*8 + 4];
            a[kt][3] = p[kt*8 + 8*68 + 4];
        }
    }

    float c[8][4];
    #pragma unroll
    for (int j = 0; j < 8; ++j){ c[j][0]=0.f; c[j][1]=0.f; c[j][2]=0.f; c[j][3]=0.f; }
    #pragma unroll
    for (int j = 0; j < 8; ++j){
        const unsigned* bpq = Bb + (64*ch + 8*j + qr)*68 + lc;
        #pragma unroll
        for (int kt = 0; kt < 8; ++kt)
            mma16816(c[j], a[kt], bpq[kt*8], bpq[kt*8 + 4]);
    }

    int b = row0 >> 10, q0 = row0 & (NN - 1);
    #pragma unroll
    for (int j = 0; j < 8; ++j){
        if (mode == 2){
            int o0 = 16*rg + qr, o1 = o0 + 8;
            int kt = (q0 >> 4) + 4*ch + (j >> 1);
            float bo0 = bs[o0], bo1 = bs[o1];
            unsigned* basep = g_V + ((((b<<6) + kt)<<3) + rg)*128 + (qr*4 + (ms>>1))*4;
            basep[(j&1)]     = h2(c[j][0]+bo0, c[j][1]+bo0);
            basep[2 + (j&1)] = h2(c[j][2]+bo1, c[j][3]+bo1);
        } else {
            int col = 64*ch + 8*j + ms;
            float b0 = bs[col], b1 = bs[col + 1];
            if (mode == 0){
                int r = row0 + 16*rg + qr;
                *(unsigned*)&g_Q[(size_t)r*NF + col]     = h2((c[j][0]+b0)*QSCALE, (c[j][1]+b1)*QSCALE);
                *(unsigned*)&g_Q[(size_t)(r+8)*NF + col] = h2((c[j][2]+b0)*QSCALE, (c[j][3]+b1)*QSCALE);
            } else {
                int hh = 4*ch + (j >> 1);
                int kt = (q0 >> 4) + rg;
                unsigned* basep = g_K + ((((b<<6) + kt)<<3) + hh)*128 + (qr*4 + (ms>>1))*4;
                basep[(j&1)]     = h2(c[j][0]+b0, c[j][1]+b1);
                basep[2 + (j&1)] = h2(c[j][2]+b0, c[j][3]+b1);
            }
        }
    }
}

// ============ kernel 2: masked flash attention + fused output projection ============
// grid 128 (b, q0-tile of 64), 512 threads: warp = (par, head)
// K/V/mask all in fragment order from gmem; no mainloop barriers or smem.
__global__ __launch_bounds__(512) void attn_kernel(const float* __restrict__ Wo,
        const float* __restrict__ bo, float* __restrict__ out){
    extern __shared__ char smem[];
    __half   (*Wos)[136]  = (__half(*)[136])(smem + SM_WOS);
    __half   (*Xs)[136]   = (__half(*)[136])(smem + SM_XS);
    float*    bs          = (float*)(smem + SM_BS);

    int tid = threadIdx.x;
    int b  = blockIdx.x >> 4;
    int qt = blockIdx.x & 15;
    int q0 = qt * 64;
    int wid = tid >> 5, lane = tid & 31;
    int h = wid & 7, par = wid >> 3;

    // stage Wo (fp32->fp16), bias
    for (int i = tid; i < 4096; i += 512){
        int r = i >> 5, c4 = (i & 31) * 4;
        float4 v = *(const float4*)&Wo[(size_t)r*NF + c4];
        uint2 u; u.x = h2(v.x, v.y); u.y = h2(v.z, v.w);
        *(uint2*)&Wos[r][c4] = u;
    }
    if (tid < 128) bs[tid] = bo[tid];

    int qr = lane >> 2;
    int lc = lane & 3;
    int ms = lc * 2;

    // Q fragments: all 4 (64 query rows) for this head
    unsigned a[4][4];
    #pragma unroll
    for (int f=0; f<4; ++f){
        const __half* Qp = g_Q + (((size_t)((b<<10) + q0 + f*16 + qr)) << 7) + h*16;
        a[f][0] = *(const unsigned*)(Qp + ms);
        a[f][2] = *(const unsigned*)(Qp + ms + 8);
        const __half* Qp8 = Qp + (8 << 7);
        a[f][1] = *(const unsigned*)(Qp8 + ms);
        a[f][3] = *(const unsigned*)(Qp8 + ms + 8);
    }

    float o[4][2][4];
    float lsum[4][4];
    #pragma unroll
    for (int f=0;f<4;++f){
        #pragma unroll
        for (int j=0;j<4;++j) lsum[f][j]=0.f;
        #pragma unroll
        for (int t=0;t<2;++t){ o[f][t][0]=0.f;o[f][t][1]=0.f;o[f][t][2]=0.f;o[f][t][3]=0.f; }
    }

    // fragment pointers: tile kt = 2t+par ; K/V stride per t = 2 tiles = 512 uint4
    const uint4* Kp = ((const uint4*)g_K) + ((((b<<6) + par)<<3) + h)*32 + lane;
    const uint4* Vp = ((const uint4*)g_V) + ((((b<<6) + par)<<3) + h)*32 + lane;
    // mask pointer: idx = ((mb*64+kt)*2+fp)*32+lane ; stride per t = 128 uint4
    const uint4* EMp = g_emask + (((size_t)(b*16 + qt)*64 + par)*2)*32 + lane;

    uint4 ka = Kp[0],   va = Vp[0];
    uint4 kb = Kp[512], vb = Vp[512];

    for (int t = 0; t < 32; ++t){
        uint4 kn, vn;
        if (t < 30){ kn = Kp[(size_t)(t+2)*512]; vn = Vp[(size_t)(t+2)*512]; }
        else       { kn = ka; vn = va; }

        // masks for this tile (all 4 f's): two coalesced LDG.128, shared by 8 head-warps
        uint4 e01 = EMp[(size_t)t*128];
        uint4 e23 = EMp[(size_t)t*128 + 32];

        #pragma unroll
        for (int f=0; f<4; ++f){
            unsigned ex = (f==0)?e01.x:(f==1)?e01.z:(f==2)?e23.x:e23.z;
            unsigned ey = (f==0)?e01.y:(f==1)?e01.w:(f==2)?e23.y:e23.w;
            unsigned d0, d1, d2, d3;
            mma16816h(d0, d1, a[f], ka.x, ka.y);
            mma16816h(d2, d3, a[f], ka.z, ka.w);
            unsigned ap[4];
            ap[0] = hmul2(hex2(d0), prmtc(ex, 0x1404u));
            ap[1] = hmul2(hex2(d1), prmtc(ex, 0x3424u));
            ap[2] = hmul2(hex2(d2), prmtc(ey, 0x1404u));
            ap[3] = hmul2(hex2(d3), prmtc(ey, 0x3424u));
            mma16816(o[f][0], ap, va.x, va.y);
            mma16816(o[f][1], ap, va.z, va.w);
            mma16816(lsum[f], ap, ONES2, ONES2);
        }
        ka = kb; va = vb; kb = kn; vb = vn;
    }

    // ---- combine parity partials via smem scratch ----
    __syncthreads();
    float* osum  = (float*)(smem + SM_SCR);                 // [64][132] f32
    float* lsums = (float*)(smem + SM_SCR + 64*132*4);      // [64][8]  f32
    if (par == 0){
        #pragma unroll
        for (int f=0; f<4; ++f){
            int r0 = f*16 + qr, r1 = r0 + 8;
            #pragma unroll
            for (int t=0; t<2; ++t){
                *(float2*)&osum[r0*132 + h*16 + t*8 + ms] = make_float2(o[f][t][0], o[f][t][1]);
                *(float2*)&osum[r1*132 + h*16 + t*8 + ms] = make_float2(o[f][t][2], o[f][t][3]);
            }
            if (lc == 0){
                lsums[r0*8 + h] = lsum[f][0];
                lsums[r1*8 + h] = lsum[f][2];
            }
        }
    }
    __syncthreads();
    if (par == 1){
        #pragma unroll
        for (int f=0; f<4; ++f){
            int r0 = f*16 + qr, r1 = r0 + 8;
            float inv0 = rcpf(lsum[f][0] + lsums[r0*8 + h]);
            float inv1 = rcpf(lsum[f][2] + lsums[r1*8 + h]);
            #pragma unroll
            for (int t=0; t<2; ++t){
                float2 p0 = *(float2*)&osum[r0*132 + h*16 + t*8 + ms];
                float2 p1 = *(float2*)&osum[r1*132 + h*16 + t*8 + ms];
                *(unsigned*)&Xs[r0][h*16 + t*8 + ms] = h2((o[f][t][0]+p0.x)*inv0, (o[f][t][1]+p0.y)*inv0);
                *(unsigned*)&Xs[r1][h*16 + t*8 + ms] = h2((o[f][t][2]+p1.x)*inv1, (o[f][t][3]+p1.y)*inv1);
            }
        }
    }
    __syncthreads();

    // ---- fused output projection: out(64x128) = Xs @ Wos^T + bo ----
    int rg = wid >> 2, cq = wid & 3;
    unsigned a2[8][4];
    {
        const unsigned* p = (const unsigned*)Xs + (16*rg + qr)*68 + lc;
        #pragma unroll
        for (int kt = 0; kt < 8; ++kt){
            a2[kt][0] = p[kt*8];
            a2[kt][1] = p[kt*8 + 8*68];
            a2[kt][2] = p[kt*8 + 4];
            a2[kt][3] = p[kt*8 + 8*68 + 4];
        }
    }
    #pragma unroll
    for (int j = 0; j < 4; ++j){
        float c[4] = {0.f,0.f,0.f,0.f};
        const unsigned* bp = (const unsigned*)Wos + (32*cq + 8*j + qr)*68 + lc;
        #pragma unroll
        for (int kt = 0; kt < 8; ++kt)
            mma16816(c, a2[kt], bp[kt*8], bp[kt*8 + 4]);
        int col = 32*cq + 8*j + ms;
        float b0 = bs[col], b1 = bs[col + 1];
        int r = (b<<10) + q0 + 16*rg + qr;
        *(float2*)&out[(size_t)r*NF + col]     = make_float2(c[0]+b0, c[1]+b1);
        *(float2*)&out[(size_t)(r+8)*NF + col] = make_float2(c[2]+b0, c[3]+b1);
    }
}

// -------- launcher --------
extern "C" void kernel_launch(void* const* d_in, const int* in_sizes, int n_in,
                              void* d_out, int out_size){
    const float* X  = (const float*)d_in[0];
    const float* A  = (const float*)d_in[1];
    const float* Wq = (const float*)d_in[2];
    const float* bq = (const float*)d_in[3];
    const float* Wk = (const float*)d_in[4];
    const float* bk = (const float*)d_in[5];
    const float* Wv = (const float*)d_in[6];
    const float* bv = (const float*)d_in[7];
    const float* Wo = (const float*)d_in[8];
    const float* bo = (const float*)d_in[9];
    float* out = (float*)d_out;

    const int SMEM1 = 70144;
    cudaFuncSetAttribute(pre_kernel,  cudaFuncAttributeMaxDynamicSharedMemorySize, SMEM1);
    cudaFuncSetAttribute(attn_kernel, cudaFuncAttributeMaxDynamicSharedMemorySize, SM_TOT);

    pre_kernel<<<320, 512, SMEM1>>>(X, A, Wq, bq, Wk, bk, Wv, bv);
    attn_kernel<<<128, 512, SM_TOT>>>(Wo, bo, out);
}